// round 2
// baseline (speedup 1.0000x reference)
#include <cuda_runtime.h>
#include <cuda_bf16.h>
#include <math.h>

// ---------------- problem constants ----------------
#define BB   4
#define CC_  256
#define HH   64
#define WW   128
#define HW   (HH*WW)          // 8192
#define HID  128
#define RR   4
#define NCORR 81              // (2R+1)^2
#define CIN1 (2*CC_ + 3 + NCORR)   // 596
#define EPS_GN 1e-5f
#define EPS_NORM 1e-12f

// ---------------- scratch (device globals; no allocations allowed) ----------------
__device__ float g_fbw [BB*CC_*HW];     // warped feat_b
__device__ float g_inva[BB*HW];         // 1/max(||a||,eps)
__device__ float g_invb[BB*HW];         // 1/max(||b_warp||,eps)
__device__ float g_corr[BB*NCORR*HW];   // correlation volume
__device__ float g_h1  [BB*HID*HW];     // conv1 out -> gn+gelu in place
__device__ float g_h2  [BB*HID*HW];     // conv2 out -> gn+gelu in place
__device__ float g_gnm[32];             // groupnorm mean   per (b,g)
__device__ float g_gni[32];             // groupnorm invstd per (b,g)

// buffer selector so kernel_launch needs no cudaGetSymbolAddress
template<int ID> __device__ __forceinline__ float* buf();
template<> __device__ __forceinline__ float* buf<1>() { return g_h1; }
template<> __device__ __forceinline__ float* buf<2>() { return g_h2; }

// ============================================================================
// Kernel 1: bilinear warp of feat_b + per-pixel channel-norms of a and b_warp
// grid (W/32, H, B), block (32,8)
// ============================================================================
__global__ void k_warp_norm(const float* __restrict__ fa,
                            const float* __restrict__ fb,
                            const float* __restrict__ flow)
{
    int x  = blockIdx.x*32 + threadIdx.x;
    int y  = blockIdx.y;
    int b  = blockIdx.z;
    int ty = threadIdx.y;
    int tx = threadIdx.x;

    float fx = flow[((b*2+0)*HH + y)*WW + x];
    float fy = flow[((b*2+1)*HH + y)*WW + x];
    float px = (float)x + fx;
    float py = (float)y + fy;
    float x0f = floorf(px), y0f = floorf(py);
    float wx = px - x0f,    wy = py - y0f;
    int x0 = (int)x0f, y0 = (int)y0f;
    int x1 = x0 + 1,   y1 = y0 + 1;

    bool vx0 = (x0 >= 0) && (x0 < WW);
    bool vx1 = (x1 >= 0) && (x1 < WW);
    bool vy0 = (y0 >= 0) && (y0 < HH);
    bool vy1 = (y1 >= 0) && (y1 < HH);
    int cx0 = min(max(x0,0),WW-1), cx1 = min(max(x1,0),WW-1);
    int cy0 = min(max(y0,0),HH-1), cy1 = min(max(y1,0),HH-1);

    float m00 = (vx0 && vy0) ? (1.f-wx)*(1.f-wy) : 0.f;
    float m01 = (vx1 && vy0) ? wx*(1.f-wy)       : 0.f;
    float m10 = (vx0 && vy1) ? (1.f-wx)*wy       : 0.f;
    float m11 = (vx1 && vy1) ? wx*wy             : 0.f;

    int i00 = cy0*WW + cx0, i01 = cy0*WW + cx1;
    int i10 = cy1*WW + cx0, i11 = cy1*WW + cx1;

    const float* fbb = fb + (size_t)b*CC_*HW;
    const float* fab = fa + (size_t)b*CC_*HW;
    int pix = y*WW + x;

    float sb = 0.f, sa = 0.f;
    for (int c = ty; c < CC_; c += 8) {
        const float* p = fbb + c*HW;
        float v = m00*p[i00] + m01*p[i01] + m10*p[i10] + m11*p[i11];
        g_fbw[((size_t)b*CC_ + c)*HW + pix] = v;
        sb += v*v;
        float va = fab[c*HW + pix];
        sa += va*va;
    }

    __shared__ float ra[8][33], rb[8][33];
    ra[ty][tx] = sa; rb[ty][tx] = sb;
    __syncthreads();
    if (ty == 0) {
        float s1 = 0.f, s2 = 0.f;
        #pragma unroll
        for (int j = 0; j < 8; j++) { s1 += ra[j][tx]; s2 += rb[j][tx]; }
        g_inva[b*HW + pix] = 1.f / fmaxf(sqrtf(s1), EPS_NORM);
        g_invb[b*HW + pix] = 1.f / fmaxf(sqrtf(s2), EPS_NORM);
    }
}

// ============================================================================
// Kernel 2: local correlation (81 offsets). grid (W/32, H/4, B), block (32,4)
// corr channel d = 80 - ((oy+4)*9 + (ox+4)) samples b at (y+oy, x+ox)
// ============================================================================
__global__ __launch_bounds__(128) void k_corr(const float* __restrict__ fa)
{
    int x0 = blockIdx.x*32;
    int y0 = blockIdx.y*4;
    int b  = blockIdx.z;
    int tx = threadIdx.x, ty = threadIdx.y;
    int tid = ty*32 + tx;

    __shared__ float sa[8][4][32];
    __shared__ float sb[8][12][40];
    __shared__ float sv[12][40];

    // stage inv-norm-b with halo (zero outside)
    for (int i = tid; i < 12*40; i += 128) {
        int r = i/40, cx = i%40;
        int gy = y0 - 4 + r, gx = x0 - 4 + cx;
        sv[r][cx] = (gy>=0 && gy<HH && gx>=0 && gx<WW) ? g_invb[b*HW + gy*WW + gx] : 0.f;
    }

    float acc[81];
    #pragma unroll
    for (int i = 0; i < 81; i++) acc[i] = 0.f;

    const float* fab = fa + (size_t)b*CC_*HW;

    for (int c0 = 0; c0 < CC_; c0 += 8) {
        __syncthreads();
        for (int i = tid; i < 8*4*32; i += 128) {
            int c = i >> 7, r = (i >> 5) & 3, cx = i & 31;
            sa[c][r][cx] = fab[(c0+c)*HW + (y0+r)*WW + (x0+cx)];
        }
        for (int i = tid; i < 8*12*40; i += 128) {
            int c = i/480, j = i%480, r = j/40, cx = j%40;
            int gy = y0 - 4 + r, gx = x0 - 4 + cx;
            sb[c][r][cx] = (gy>=0 && gy<HH && gx>=0 && gx<WW)
                         ? g_fbw[((size_t)b*CC_ + c0 + c)*HW + gy*WW + gx] : 0.f;
        }
        __syncthreads();
        #pragma unroll 2
        for (int c = 0; c < 8; c++) {
            float av = sa[c][ty][tx];
            #pragma unroll
            for (int sy = 0; sy < 9; sy++) {
                const float* brp = &sb[c][ty+sy][tx];
                #pragma unroll
                for (int sx = 0; sx < 9; sx++)
                    acc[sy*9+sx] += av * brp[sx];
            }
        }
    }

    float ia = g_inva[b*HW + (y0+ty)*WW + (x0+tx)];
    int pix = (y0+ty)*WW + (x0+tx);
    #pragma unroll
    for (int i = 0; i < 81; i++) {
        int sy = i/9, sx = i%9;
        float val = acc[i] * ia * sv[ty+sy][tx+sx];
        g_corr[((size_t)b*NCORR + (80 - i))*HW + pix] = val;
    }
}

// ============================================================================
// conv 3x3 (pad 1) as register-blocked implicit GEMM.
// grid (W/32, H, B), block 256. Warp w computes out-ch [16w,16w+16) for 32 px.
// ============================================================================
__device__ __forceinline__ float concat_fetch(const float* __restrict__ fa,
                                              const float* __restrict__ flow,
                                              const float* __restrict__ conf,
                                              int b, int c, int y, int x)
{
    if (y < 0 || y >= HH || x < 0 || x >= WW) return 0.f;
    int p = y*WW + x;
    if (c < 256)  return fa[((size_t)b*CC_ + c)*HW + p];
    if (c < 512)  return g_fbw[((size_t)b*CC_ + (c-256))*HW + p];
    if (c < 514)  return flow[((size_t)b*2 + (c-512))*HW + p];
    if (c == 514) return conf[(size_t)b*HW + p];
    return g_corr[((size_t)b*NCORR + (c-515))*HW + p];
}

template<int CIN, bool CONCAT, int DST>
__global__ __launch_bounds__(256) void k_conv3x3(const float* __restrict__ wgt,
                                                 const float* __restrict__ bias,
                                                 const float* __restrict__ fa,
                                                 const float* __restrict__ flow,
                                                 const float* __restrict__ conf)
{
    constexpr int NCHUNK = CIN / 4;
    float* __restrict__ out = buf<DST>();
    const float* __restrict__ in = CONCAT ? nullptr : g_h1;

    int x0 = blockIdx.x*32;
    int y  = blockIdx.y;
    int b  = blockIdx.z;
    int tid  = threadIdx.x;
    int lane = tid & 31;
    int wrp  = tid >> 5;
    int ocb  = wrp * 16;

    __shared__ float sW[128][4][12];   // [oc][chan-in-chunk][tap(9), pad to 12]
    __shared__ float sIn[4][3][36];    // 34 cols used (x0-1 .. x0+32)

    float acc[16];
    #pragma unroll
    for (int i = 0; i < 16; i++) acc[i] = 0.f;

    for (int ch = 0; ch < NCHUNK; ch++) {
        int c0 = ch*4;
        // ---- stage weights: thread = (oc = tid>>1, half = tid&1) ----
        {
            int oc = tid >> 1, half = tid & 1;
            const float* gw = wgt + (size_t)oc*(CIN*9) + c0*9;
            if (half == 0) {
                #pragma unroll
                for (int k = 0; k < 4; k++) {
                    float4 v = *(const float4*)(gw + k*4);
                    int j = k*4;
                    sW[oc][(j  )/9][(j  )%9] = v.x;
                    sW[oc][(j+1)/9][(j+1)%9] = v.y;
                    sW[oc][(j+2)/9][(j+2)%9] = v.z;
                    sW[oc][(j+3)/9][(j+3)%9] = v.w;
                }
            } else {
                #pragma unroll
                for (int k = 0; k < 5; k++) {
                    float4 v = *(const float4*)(gw + 16 + k*4);
                    int j = 16 + k*4;
                    sW[oc][(j  )/9][(j  )%9] = v.x;
                    sW[oc][(j+1)/9][(j+1)%9] = v.y;
                    sW[oc][(j+2)/9][(j+2)%9] = v.z;
                    sW[oc][(j+3)/9][(j+3)%9] = v.w;
                }
            }
        }
        // ---- stage input tile (4 ch x 3 rows x 34 cols) ----
        for (int i = tid; i < 4*3*34; i += 256) {
            int c = i/102, r2 = i%102, dy = r2/34, j = r2%34;
            int gy = y - 1 + dy, gx = x0 - 1 + j;
            float v;
            if (CONCAT) v = concat_fetch(fa, flow, conf, b, c0+c, gy, gx);
            else        v = (gy>=0 && gy<HH && gx>=0 && gx<WW)
                            ? in[((size_t)b*CIN + c0 + c)*HW + gy*WW + gx] : 0.f;
            sIn[c][dy][j] = v;
        }
        __syncthreads();
        // ---- compute ----
        #pragma unroll
        for (int cc = 0; cc < 4; cc++) {
            float r0[3], r1[3], r2v[3];
            #pragma unroll
            for (int d = 0; d < 3; d++) {
                r0[d]  = sIn[cc][0][lane+d];
                r1[d]  = sIn[cc][1][lane+d];
                r2v[d] = sIn[cc][2][lane+d];
            }
            #pragma unroll
            for (int i = 0; i < 16; i++) {
                const float4* wp = (const float4*)&sW[ocb+i][cc][0];
                float4 wa = wp[0];
                float4 wb = wp[1];
                float  w8 = sW[ocb+i][cc][8];
                acc[i] += wa.x*r0[0] + wa.y*r0[1] + wa.z*r0[2]
                        + wa.w*r1[0] + wb.x*r1[1] + wb.y*r1[2]
                        + wb.z*r2v[0]+ wb.w*r2v[1]+ w8*r2v[2];
            }
        }
        __syncthreads();
    }
    int x = x0 + lane;
    #pragma unroll
    for (int i = 0; i < 16; i++) {
        int oc = ocb + i;
        out[((size_t)b*HID + oc)*HW + y*WW + x] = acc[i] + bias[oc];
    }
}

// ============================================================================
// GroupNorm stats: one block per (b,g); 16 ch * 8192 px = 131072 elems
// ============================================================================
template<int SRC>
__global__ __launch_bounds__(256) void k_gnstats()
{
    const float* __restrict__ h = buf<SRC>();
    int bg = blockIdx.x;           // 0..31
    int b = bg >> 3, g = bg & 7;
    const float* p = h + ((size_t)b*HID + g*16)*HW;
    int tid = threadIdx.x;
    float s = 0.f, q = 0.f;
    for (int i = tid; i < 16*HW; i += 256) {
        float v = p[i];
        s += v; q += v*v;
    }
    __shared__ float rs[256], rq[256];
    rs[tid] = s; rq[tid] = q;
    __syncthreads();
    for (int off = 128; off > 0; off >>= 1) {
        if (tid < off) { rs[tid] += rs[tid+off]; rq[tid] += rq[tid+off]; }
        __syncthreads();
    }
    if (tid == 0) {
        const float inv_n = 1.f / (16.f*HW);
        float m  = rs[0] * inv_n;
        float var = rq[0] * inv_n - m*m;
        g_gnm[bg] = m;
        g_gni[bg] = rsqrtf(var + EPS_GN);
    }
}

// GN apply + exact GELU, in place. grid 16384 x 256
template<int SRC>
__global__ __launch_bounds__(256) void k_gnapply(const float* __restrict__ sc,
                                                 const float* __restrict__ bi)
{
    float* __restrict__ h = buf<SRC>();
    int idx = blockIdx.x*256 + threadIdx.x;   // < 4*128*8192
    int ch = (idx >> 13) & 127;
    int b  = idx >> 20;                        // /(128*8192)
    int bg = b*8 + (ch >> 4);
    float m = g_gnm[bg], is = g_gni[bg];
    float v = (h[idx] - m) * is * sc[ch] + bi[ch];
    h[idx] = 0.5f * v * (1.f + erff(v * 0.70710678118654752440f));
}

// ============================================================================
// Heads: delta(2ch, tanh) + confidence(1ch, sigmoid) fused direct conv
// grid (W/32, H/8, B), block (32,8)
// ============================================================================
__global__ __launch_bounds__(256) void k_head(const float* __restrict__ wd,
                                              const float* __restrict__ bd,
                                              const float* __restrict__ wc,
                                              const float* __restrict__ bc,
                                              float* __restrict__ out)
{
    int x0 = blockIdx.x*32;
    int y0 = blockIdx.y*8;
    int b  = blockIdx.z;
    int tx = threadIdx.x, ty = threadIdx.y;
    int tid = ty*32 + tx;

    __shared__ float sw[3456];          // [oc0:1152][oc1:1152][occ:1152], layout c*9+t
    __shared__ float st[8][10][34];

    for (int i = tid; i < 3456; i += 256)
        sw[i] = (i < 2304) ? wd[i] : wc[i - 2304];

    float a0 = bd[0], a1 = bd[1], a2 = bc[0];

    for (int c0 = 0; c0 < HID; c0 += 8) {
        __syncthreads();
        for (int i = tid; i < 8*10*34; i += 256) {
            int c = i/340, r2 = i%340, r = r2/34, j = r2%34;
            int gy = y0 - 1 + r, gx = x0 - 1 + j;
            st[c][r][j] = (gy>=0 && gy<HH && gx>=0 && gx<WW)
                        ? g_h2[((size_t)b*HID + c0 + c)*HW + gy*WW + gx] : 0.f;
        }
        __syncthreads();
        #pragma unroll 2
        for (int c = 0; c < 8; c++) {
            float p[9];
            #pragma unroll
            for (int dy = 0; dy < 3; dy++)
                #pragma unroll
                for (int dx = 0; dx < 3; dx++)
                    p[dy*3+dx] = st[c][ty+dy][tx+dx];
            int cw = (c0 + c)*9;
            #pragma unroll
            for (int t = 0; t < 9; t++) {
                a0 += sw[cw + t]        * p[t];
                a1 += sw[1152 + cw + t] * p[t];
                a2 += sw[2304 + cw + t] * p[t];
            }
        }
    }
    int pix = (y0+ty)*WW + (x0+tx);
    out[((size_t)b*2 + 0)*HW + pix] = tanhf(a0);
    out[((size_t)b*2 + 1)*HW + pix] = tanhf(a1);
    out[(size_t)BB*2*HW + (size_t)b*HW + pix] = 1.f / (1.f + expf(-a2));
}

// ============================================================================
// launch — pure kernel launches only (graph-capturable, no API calls)
// ============================================================================
extern "C" void kernel_launch(void* const* d_in, const int* in_sizes, int n_in,
                              void* d_out, int out_size)
{
    const float* fa   = (const float*)d_in[0];
    const float* fb   = (const float*)d_in[1];
    const float* flow = (const float*)d_in[2];
    const float* conf = (const float*)d_in[3];
    const float* w1   = (const float*)d_in[4];
    const float* b1   = (const float*)d_in[5];
    const float* g1s  = (const float*)d_in[6];
    const float* g1b  = (const float*)d_in[7];
    const float* w2   = (const float*)d_in[8];
    const float* b2   = (const float*)d_in[9];
    const float* g2s  = (const float*)d_in[10];
    const float* g2b  = (const float*)d_in[11];
    const float* wd   = (const float*)d_in[12];
    const float* bd   = (const float*)d_in[13];
    const float* wc   = (const float*)d_in[14];
    const float* bc   = (const float*)d_in[15];
    float* out = (float*)d_out;

    k_warp_norm<<<dim3(WW/32, HH, BB), dim3(32,8)>>>(fa, fb, flow);
    k_corr<<<dim3(WW/32, HH/4, BB), dim3(32,4)>>>(fa);
    k_conv3x3<CIN1, true , 1><<<dim3(WW/32, HH, BB), 256>>>(w1, b1, fa, flow, conf);
    k_gnstats<1><<<32, 256>>>();
    k_gnapply<1><<<(BB*HID*HW)/256, 256>>>(g1s, g1b);
    k_conv3x3<HID, false, 2><<<dim3(WW/32, HH, BB), 256>>>(w2, b2, fa, flow, conf);
    k_gnstats<2><<<32, 256>>>();
    k_gnapply<2><<<(BB*HID*HW)/256, 256>>>(g2s, g2b);
    k_head<<<dim3(WW/32, HH/8, BB), dim3(32,8)>>>(wd, bd, wc, bc, out);
}